// round 12
// baseline (speedup 1.0000x reference)
// R12: fused collection with CHUNK-LOCAL threshold (chunk_min + band).
// Removes R11's per-chunk second barrier + smem rowmin atomics while keeping
// the g_dist elimination. Superset proof: any exact-min/tie code t satisfies
// approx(t) <= chunkmin(t's chunk) + 2*err <= chunkmin + band.
#include <cuda_runtime.h>
#include <cuda_bf16.h>
#include <cstdint>

#define D_DIM 256
#define K_CODES 1024
#define HW 1024
#define N_ROWS 32768
#define AROW 264                   // padded bf16 row stride (528B)

// ---- global scratch (allocations forbidden; device globals sanctioned) ----
__device__ __nv_bfloat16 g_zbf[N_ROWS * D_DIM];   // z transposed, bf16
__device__ float         g_zf [N_ROWS * D_DIM];   // z transposed, fp32
__device__ __nv_bfloat16 g_ebf[K_CODES * D_DIM];  // codebook bf16
__device__ float         g_e2 [K_CODES];          // exact ||e||^2
__device__ float         g_sz [N_ROWS];           // exact ||z||^2 (sequential d)
__device__ int           g_ccnt[N_ROWS];          // candidate counts
__device__ unsigned short g_cand[(size_t)N_ROWS * K_CODES]; // candidate lists
__device__ unsigned      g_code[N_ROWS];          // final argmin codes

// ---- prep: exact e2 (identical recipe since R1) + bf16 codebook ----
__global__ void vq_prep(const float* __restrict__ emb) {
    const int j = blockIdx.x;
    const int d = threadIdx.x;
    float v = emb[j * D_DIM + d];
    g_ebf[j * D_DIM + d] = __float2bfloat16(v);
    float s = __fmul_rn(v, v);
    #pragma unroll
    for (int o = 16; o > 0; o >>= 1)
        s = __fadd_rn(s, __shfl_down_sync(0xFFFFFFFFu, s, o));
    __shared__ float ws[8];
    if ((d & 31) == 0) ws[d >> 5] = s;
    __syncthreads();
    if (d == 0) {
        float t = ws[0];
        #pragma unroll
        for (int w = 1; w < 8; w++) t = __fadd_rn(t, ws[w]);
        g_e2[j] = t;
    }
}

// ---- z transpose: [b][d][hw] -> [n][d] (fp32 + bf16), smem-tiled ----
__global__ void zt_kernel(const float* __restrict__ z) {
    __shared__ float ts[64][65];
    const int hw0 = blockIdx.x * 64;
    const int d0  = blockIdx.y * 64;
    const int b   = blockIdx.z;
    const int t = threadIdx.x;
    {
        const int dr = t >> 2, c4 = (t & 3) * 16;
        const float* src = z + ((size_t)b * D_DIM + d0 + dr) * HW + hw0 + c4;
        #pragma unroll
        for (int u = 0; u < 4; u++) {
            float4 v = *(const float4*)(src + u * 4);
            ts[dr][c4 + u * 4 + 0] = v.x;
            ts[dr][c4 + u * 4 + 1] = v.y;
            ts[dr][c4 + u * 4 + 2] = v.z;
            ts[dr][c4 + u * 4 + 3] = v.w;
        }
    }
    __syncthreads();
    {
        const int hwr = t >> 2, dc = (t & 3) * 16;
        const size_t n = (size_t)b * HW + hw0 + hwr;
        float* dstf = g_zf + n * D_DIM + d0 + dc;
        __nv_bfloat16* dstb = g_zbf + n * D_DIM + d0 + dc;
        #pragma unroll
        for (int u = 0; u < 4; u++) {
            float x0 = ts[dc + u * 4 + 0][hwr];
            float x1 = ts[dc + u * 4 + 1][hwr];
            float x2 = ts[dc + u * 4 + 2][hwr];
            float x3 = ts[dc + u * 4 + 3][hwr];
            float4 f4; f4.x = x0; f4.y = x1; f4.z = x2; f4.w = x3;
            *(float4*)(dstf + u * 4) = f4;
            __nv_bfloat162 p0, p1;
            p0.x = __float2bfloat16(x0); p0.y = __float2bfloat16(x1);
            p1.x = __float2bfloat16(x2); p1.y = __float2bfloat16(x3);
            *(__nv_bfloat162*)(dstb + u * 4 + 0) = p0;
            *(__nv_bfloat162*)(dstb + u * 4 + 2) = p1;
        }
    }
}

// ---- exact ||z||^2 (sequential d) + per-launch reset of g_ccnt ----
__global__ void sz_kernel(const float* __restrict__ z) {
    const int nb = blockIdx.x * 128;
    const int b = nb / HW;
    const int hwb = nb % HW;
    const float* zp = z + (size_t)b * (D_DIM * HW) + hwb + threadIdx.x;
    float s = 0.f;
    for (int d = 0; d < D_DIM; d++) {
        float v = zp[(size_t)d * HW];
        s = __fadd_rn(s, __fmul_rn(v, v));
    }
    g_sz[nb + threadIdx.x] = s;
    g_ccnt[nb + threadIdx.x] = 0;     // reset for this launch (graph replay)
}

__device__ __forceinline__ void cp_async16(uint32_t dst, const void* src) {
    asm volatile("cp.async.cg.shared.global [%0], [%1], 16;\n" :: "r"(dst), "l"(src));
}
__device__ __forceinline__ void cp_commit() {
    asm volatile("cp.async.commit_group;\n" ::: "memory");
}
__device__ __forceinline__ void cp_wait0() {
    asm volatile("cp.async.wait_group 0;\n" ::: "memory");
}

__device__ __forceinline__ void mma_bf16(float* c, uint32_t a0, uint32_t a1,
                                         uint32_t a2, uint32_t a3,
                                         uint32_t b0, uint32_t b1) {
    asm volatile(
        "mma.sync.aligned.m16n8k16.row.col.f32.bf16.bf16.f32 "
        "{%0,%1,%2,%3}, {%4,%5,%6,%7}, {%8,%9}, {%0,%1,%2,%3};\n"
        : "+f"(c[0]), "+f"(c[1]), "+f"(c[2]), "+f"(c[3])
        : "r"(a0), "r"(a1), "r"(a2), "r"(a3), "r"(b0), "r"(b1));
}

// ---- pass 1: bf16 MMA + chunk-local candidate collection (1 sync/chunk) ----
#define SMEM_AS 0
#define SMEM_BS (128 * AROW * 2)                 // 67584
#define SMEM_SZ (SMEM_BS + 64 * AROW * 2)        // 101376
#define SMEM_E2 (SMEM_SZ + 128 * 4)              // 101888
#define SMEM_BD (SMEM_E2 + 64 * 4)               // 102144 band per row
#define SMEM_C_TOTAL (SMEM_BD + 128 * 4)         // 102656

__global__ void __launch_bounds__(256, 2) mma_kernel() {
    extern __shared__ char cs[];
    __nv_bfloat16* As = (__nv_bfloat16*)(cs + SMEM_AS);   // [128][264]
    __nv_bfloat16* Bs = (__nv_bfloat16*)(cs + SMEM_BS);   // [64][264]
    float* szs = (float*)(cs + SMEM_SZ);
    float* e2s = (float*)(cs + SMEM_E2);
    float* bandv = (float*)(cs + SMEM_BD);

    const int t = threadIdx.x;
    const int w = t >> 5;
    const int l = t & 31;
    const int nbase = blockIdx.x * 128;
    const uint32_t as_s = (uint32_t)__cvta_generic_to_shared(As);
    const uint32_t bs_s = (uint32_t)__cvta_generic_to_shared(Bs);

    #pragma unroll
    for (int i = 0; i < 16; i++) {
        int idx = t + 256 * i;
        int row = idx >> 5;
        int off = (idx & 31) * 16;
        cp_async16(as_s + row * (AROW * 2) + off,
                   (const char*)(g_zbf + (size_t)(nbase + row) * D_DIM) + off);
    }
    if (t < 128) {
        float sz = g_sz[nbase + t];
        szs[t] = sz;
        // Rigorous bf16 band (>= 2x worst-case dist err, with 2x safety):
        bandv[t] = 5e-4f * sqrtf(sz) + 2e-4f;
    }
    cp_commit();

    const int rsub = w * 16 + (l >> 2);       // row A; row B = rsub + 8

    for (int c = 0; c < 16; c++) {
        #pragma unroll
        for (int i = 0; i < 8; i++) {
            int idx = t + 256 * i;
            int row = idx >> 5;
            int off = (idx & 31) * 16;
            cp_async16(bs_s + row * (AROW * 2) + off,
                       (const char*)(g_ebf + (size_t)(c * 64 + row) * D_DIM) + off);
        }
        cp_commit();
        if (t < 64) e2s[t] = g_e2[c * 64 + t];
        cp_wait0();
        __syncthreads();

        float acc[8][4];
        #pragma unroll
        for (int tt = 0; tt < 8; tt++)
            #pragma unroll
            for (int u = 0; u < 4; u++) acc[tt][u] = 0.f;

        #pragma unroll
        for (int k16 = 0; k16 < 16; k16++) {
            const int k0 = k16 * 16 + (l & 3) * 2;
            uint32_t a0 = *(const uint32_t*)(As + rsub * AROW + k0);
            uint32_t a1 = *(const uint32_t*)(As + (rsub + 8) * AROW + k0);
            uint32_t a2 = *(const uint32_t*)(As + rsub * AROW + k0 + 8);
            uint32_t a3 = *(const uint32_t*)(As + (rsub + 8) * AROW + k0 + 8);
            #pragma unroll
            for (int tt = 0; tt < 8; tt++) {
                const int bn = tt * 8 + (l >> 2);
                uint32_t b0 = *(const uint32_t*)(Bs + bn * AROW + k0);
                uint32_t b1 = *(const uint32_t*)(Bs + bn * AROW + k0 + 8);
                mma_bf16(acc[tt], a0, a1, a2, a3, b0, b1);
            }
        }

        // chunk dists (16 per lane) + chunk-local 64-code min per row
        float dAv[8][2], dBv[8][2];
        float mA = 3.402823466e38f, mB = 3.402823466e38f;
        {
            const float szA = szs[rsub], szB = szs[rsub + 8];
            #pragma unroll
            for (int tt = 0; tt < 8; tt++) {
                const int nl = tt * 8 + 2 * (l & 3);
                const float e2a = e2s[nl], e2b = e2s[nl + 1];
                dAv[tt][0] = __fmaf_rn(-2.0f, acc[tt][0], szA + e2a);
                dAv[tt][1] = __fmaf_rn(-2.0f, acc[tt][1], szA + e2b);
                dBv[tt][0] = __fmaf_rn(-2.0f, acc[tt][2], szB + e2a);
                dBv[tt][1] = __fmaf_rn(-2.0f, acc[tt][3], szB + e2b);
                mA = fminf(mA, fminf(dAv[tt][0], dAv[tt][1]));
                mB = fminf(mB, fminf(dBv[tt][0], dBv[tt][1]));
            }
        }
        #pragma unroll
        for (int o = 1; o < 4; o <<= 1) {
            mA = fminf(mA, __shfl_xor_sync(0xFFFFFFFFu, mA, o));
            mB = fminf(mB, __shfl_xor_sync(0xFFFFFFFFu, mB, o));
        }

        // collect: approx <= chunk_min + band (superset; no barrier needed)
        {
            const float thA = mA + bandv[rsub];
            const float thB = mB + bandv[rsub + 8];
            #pragma unroll
            for (int tt = 0; tt < 8; tt++) {
                const int n0 = c * 64 + tt * 8 + 2 * (l & 3);
                #pragma unroll
                for (int h = 0; h < 2; h++) {
                    if (dAv[tt][h] <= thA) {
                        int p = atomicAdd(&g_ccnt[nbase + rsub], 1);
                        g_cand[(size_t)(nbase + rsub) * K_CODES + p] =
                            (unsigned short)(n0 + h);
                    }
                    if (dBv[tt][h] <= thB) {
                        int p = atomicAdd(&g_ccnt[nbase + rsub + 8], 1);
                        g_cand[(size_t)(nbase + rsub + 8) * K_CODES + p] =
                            (unsigned short)(n0 + h);
                    }
                }
            }
        }
        __syncthreads();   // protect Bs/e2s before next chunk's writes
    }
}

// ---- pass 2: exact warp-cooperative rescore of the candidate lists ----
__global__ void argmin_kernel(const float* __restrict__ emb,
                              float* __restrict__ idxf) {
    const int wrp = threadIdx.x >> 5;
    const int row = blockIdx.x * 8 + wrp;
    const int l = threadIdx.x & 31;

    const int cnt = g_ccnt[row];
    const float sz = g_sz[row];
    const float* zr = g_zf + (size_t)row * D_DIM;
    float zseg[8];
    #pragma unroll
    for (int u = 0; u < 8; u++) zseg[u] = zr[l * 8 + u];

    const unsigned short* cl = g_cand + (size_t)row * K_CODES;
    unsigned long long best = ~0ULL;
    for (int ci = 0; ci < cnt; ci++) {
        const int code = cl[ci];
        const float* er = emb + (size_t)code * D_DIM + l * 8;
        float part = 0.f;
        #pragma unroll
        for (int u = 0; u < 8; u++)
            part = __fmaf_rn(zseg[u], __ldg(&er[u]), part);
        #pragma unroll
        for (int o = 16; o > 0; o >>= 1)
            part = __fadd_rn(part, __shfl_xor_sync(0xFFFFFFFFu, part, o));
        float tt = __fadd_rn(sz, g_e2[code]);
        float dist = __fmaf_rn(-2.0f, part, tt);
        unsigned fb = __float_as_uint(dist);
        fb = (fb & 0x80000000u) ? ~fb : (fb | 0x80000000u);
        unsigned long long p =
            ((unsigned long long)fb << 32) | (unsigned long long)code;
        if (p < best) best = p;    // lowest dist, lowest code on ties
    }
    if (l == 0) {
        const unsigned code = (unsigned)(best & 0xFFFFFFFFu);
        g_code[row] = code;
        idxf[row] = (float)code;
    }
}

// ---- epilogue: zq + loss (identical since R7) ----
__global__ void epi_kernel(const float* __restrict__ z,
                           const float* __restrict__ emb,
                           float* __restrict__ zq, float* __restrict__ loss) {
    const int nbase = blockIdx.x * 128;
    const int b = nbase / HW;
    const int hwbase = nbase % HW;
    const float* zb = z + (size_t)b * (D_DIM * HW) + hwbase;
    const int tid = threadIdx.x;
    const int r = tid & 127;
    const int half = tid >> 7;
    const int n = nbase + r;
    const unsigned code = g_code[n];
    const float* erow = emb + (size_t)code * D_DIM;
    float* zqb = zq + (size_t)b * (D_DIM * HW) + hwbase;
    float* lrow = loss + (size_t)n * D_DIM;
    #pragma unroll 4
    for (int sft = 0; sft < D_DIM / 2; sft++) {
        const int d = half * (D_DIM / 2) + sft;
        float zv = zb[(size_t)d * HW + r];
        float ev = __ldg(&erow[d]);
        zqb[(size_t)d * HW + r] = ev;
        float df = __fadd_rn(ev, -zv);
        lrow[d] = __fmul_rn(df, df);
    }
}

extern "C" void kernel_launch(void* const* d_in, const int* in_sizes, int n_in,
                              void* d_out, int out_size) {
    const float* z   = (const float*)d_in[0];   // [32,256,32,32]
    const float* emb = (const float*)d_in[1];   // [1024,256]
    float* out = (float*)d_out;

    const int n_z = in_sizes[0];                // 8388608
    const int N = n_z / D_DIM;                  // 32768

    float* zq   = out;
    float* idxf = out + n_z;
    float* loss = out + n_z + N;

    cudaFuncSetAttribute(mma_kernel,
                         cudaFuncAttributeMaxDynamicSharedMemorySize,
                         SMEM_C_TOTAL);

    vq_prep<<<K_CODES, D_DIM>>>(emb);
    zt_kernel<<<dim3(HW / 64, D_DIM / 64, 32), 256>>>(z);
    sz_kernel<<<N / 128, 128>>>(z);
    mma_kernel<<<N / 128, 256, SMEM_C_TOTAL>>>();
    argmin_kernel<<<N / 8, 256>>>(emb, idxf);
    epi_kernel<<<N / 128, 256>>>(z, emb, zq, loss);
}

// round 13
// speedup vs baseline: 2.7405x; 2.7405x over previous
// R13: R10 architecture restored (best: 284.5us), with g_dist halved —
// store s = e2 - 2*dot as fp16 (sz cancels in argmin). Band 8.2e-3 covers
// bf16 MMA err (<=2e-3) + fp16 quantization (<=2.4e-4) with 2x slack.
// Rescore pass bit-identical to R10 (exact fp32, packed-u64 tie-break).
#include <cuda_runtime.h>
#include <cuda_bf16.h>
#include <cuda_fp16.h>
#include <cstdint>

#define D_DIM 256
#define K_CODES 1024
#define HW 1024
#define N_ROWS 32768
#define AROW 264                   // padded bf16 row stride (528B)

// ---- global scratch (allocations forbidden; device globals sanctioned) ----
__device__ __nv_bfloat16 g_zbf[N_ROWS * D_DIM];   // z transposed, bf16
__device__ float         g_zf [N_ROWS * D_DIM];   // z transposed, fp32
__device__ __nv_bfloat16 g_ebf[K_CODES * D_DIM];  // codebook bf16
__device__ float         g_e2 [K_CODES];          // exact ||e||^2
__device__ float         g_sz [N_ROWS];           // exact ||z||^2 (sequential d)
__device__ __half        g_dh [(size_t)N_ROWS * K_CODES]; // s = e2-2dot (67MB)
__device__ unsigned      g_code[N_ROWS];          // final argmin codes

// ---- prep: exact e2 (identical recipe since R1) + bf16 codebook ----
__global__ void vq_prep(const float* __restrict__ emb) {
    const int j = blockIdx.x;
    const int d = threadIdx.x;
    float v = emb[j * D_DIM + d];
    g_ebf[j * D_DIM + d] = __float2bfloat16(v);
    float s = __fmul_rn(v, v);
    #pragma unroll
    for (int o = 16; o > 0; o >>= 1)
        s = __fadd_rn(s, __shfl_down_sync(0xFFFFFFFFu, s, o));
    __shared__ float ws[8];
    if ((d & 31) == 0) ws[d >> 5] = s;
    __syncthreads();
    if (d == 0) {
        float t = ws[0];
        #pragma unroll
        for (int w = 1; w < 8; w++) t = __fadd_rn(t, ws[w]);
        g_e2[j] = t;
    }
}

// ---- z transpose: [b][d][hw] -> [n][d] (fp32 + bf16), smem-tiled ----
__global__ void zt_kernel(const float* __restrict__ z) {
    __shared__ float ts[64][65];
    const int hw0 = blockIdx.x * 64;
    const int d0  = blockIdx.y * 64;
    const int b   = blockIdx.z;
    const int t = threadIdx.x;
    {
        const int dr = t >> 2, c4 = (t & 3) * 16;
        const float* src = z + ((size_t)b * D_DIM + d0 + dr) * HW + hw0 + c4;
        #pragma unroll
        for (int u = 0; u < 4; u++) {
            float4 v = *(const float4*)(src + u * 4);
            ts[dr][c4 + u * 4 + 0] = v.x;
            ts[dr][c4 + u * 4 + 1] = v.y;
            ts[dr][c4 + u * 4 + 2] = v.z;
            ts[dr][c4 + u * 4 + 3] = v.w;
        }
    }
    __syncthreads();
    {
        const int hwr = t >> 2, dc = (t & 3) * 16;
        const size_t n = (size_t)b * HW + hw0 + hwr;
        float* dstf = g_zf + n * D_DIM + d0 + dc;
        __nv_bfloat16* dstb = g_zbf + n * D_DIM + d0 + dc;
        #pragma unroll
        for (int u = 0; u < 4; u++) {
            float x0 = ts[dc + u * 4 + 0][hwr];
            float x1 = ts[dc + u * 4 + 1][hwr];
            float x2 = ts[dc + u * 4 + 2][hwr];
            float x3 = ts[dc + u * 4 + 3][hwr];
            float4 f4; f4.x = x0; f4.y = x1; f4.z = x2; f4.w = x3;
            *(float4*)(dstf + u * 4) = f4;
            __nv_bfloat162 p0, p1;
            p0.x = __float2bfloat16(x0); p0.y = __float2bfloat16(x1);
            p1.x = __float2bfloat16(x2); p1.y = __float2bfloat16(x3);
            *(__nv_bfloat162*)(dstb + u * 4 + 0) = p0;
            *(__nv_bfloat162*)(dstb + u * 4 + 2) = p1;
        }
    }
}

// ---- exact ||z||^2, sequential over d (identical to R7) ----
__global__ void sz_kernel(const float* __restrict__ z) {
    const int nb = blockIdx.x * 128;
    const int b = nb / HW;
    const int hwb = nb % HW;
    const float* zp = z + (size_t)b * (D_DIM * HW) + hwb + threadIdx.x;
    float s = 0.f;
    for (int d = 0; d < D_DIM; d++) {
        float v = zp[(size_t)d * HW];
        s = __fadd_rn(s, __fmul_rn(v, v));
    }
    g_sz[nb + threadIdx.x] = s;
}

__device__ __forceinline__ void cp_async16(uint32_t dst, const void* src) {
    asm volatile("cp.async.cg.shared.global [%0], [%1], 16;\n" :: "r"(dst), "l"(src));
}
__device__ __forceinline__ void cp_commit() {
    asm volatile("cp.async.commit_group;\n" ::: "memory");
}
__device__ __forceinline__ void cp_wait0() {
    asm volatile("cp.async.wait_group 0;\n" ::: "memory");
}

__device__ __forceinline__ void mma_bf16(float* c, uint32_t a0, uint32_t a1,
                                         uint32_t a2, uint32_t a3,
                                         uint32_t b0, uint32_t b1) {
    asm volatile(
        "mma.sync.aligned.m16n8k16.row.col.f32.bf16.bf16.f32 "
        "{%0,%1,%2,%3}, {%4,%5,%6,%7}, {%8,%9}, {%0,%1,%2,%3};\n"
        : "+f"(c[0]), "+f"(c[1]), "+f"(c[2]), "+f"(c[3])
        : "r"(a0), "r"(a1), "r"(a2), "r"(a3), "r"(b0), "r"(b1));
}

// ---- pass 1: bf16 MMA -> s = e2 - 2*dot stored as fp16 ----
#define SMEM_AS 0
#define SMEM_BS (128 * AROW * 2)                 // 67584
#define SMEM_E2 (SMEM_BS + 64 * AROW * 2)        // 101376
#define SMEM_C_TOTAL (SMEM_E2 + 64 * 4)          // 101632

__global__ void __launch_bounds__(256, 2) mma_kernel() {
    extern __shared__ char cs[];
    __nv_bfloat16* As = (__nv_bfloat16*)(cs + SMEM_AS);   // [128][264]
    __nv_bfloat16* Bs = (__nv_bfloat16*)(cs + SMEM_BS);   // [64][264]
    float* e2s = (float*)(cs + SMEM_E2);

    const int t = threadIdx.x;
    const int w = t >> 5;
    const int l = t & 31;
    const int nbase = blockIdx.x * 128;
    const uint32_t as_s = (uint32_t)__cvta_generic_to_shared(As);
    const uint32_t bs_s = (uint32_t)__cvta_generic_to_shared(Bs);

    #pragma unroll
    for (int i = 0; i < 16; i++) {
        int idx = t + 256 * i;
        int row = idx >> 5;
        int off = (idx & 31) * 16;
        cp_async16(as_s + row * (AROW * 2) + off,
                   (const char*)(g_zbf + (size_t)(nbase + row) * D_DIM) + off);
    }
    cp_commit();

    const int rsub = w * 16 + (l >> 2);

    for (int c = 0; c < 16; c++) {
        #pragma unroll
        for (int i = 0; i < 8; i++) {
            int idx = t + 256 * i;
            int row = idx >> 5;
            int off = (idx & 31) * 16;
            cp_async16(bs_s + row * (AROW * 2) + off,
                       (const char*)(g_ebf + (size_t)(c * 64 + row) * D_DIM) + off);
        }
        cp_commit();
        if (t < 64) e2s[t] = g_e2[c * 64 + t];
        cp_wait0();
        __syncthreads();

        float acc[8][4];
        #pragma unroll
        for (int tt = 0; tt < 8; tt++)
            #pragma unroll
            for (int u = 0; u < 4; u++) acc[tt][u] = 0.f;

        #pragma unroll
        for (int k16 = 0; k16 < 16; k16++) {
            const int k0 = k16 * 16 + (l & 3) * 2;
            uint32_t a0 = *(const uint32_t*)(As + rsub * AROW + k0);
            uint32_t a1 = *(const uint32_t*)(As + (rsub + 8) * AROW + k0);
            uint32_t a2 = *(const uint32_t*)(As + rsub * AROW + k0 + 8);
            uint32_t a3 = *(const uint32_t*)(As + (rsub + 8) * AROW + k0 + 8);
            #pragma unroll
            for (int tt = 0; tt < 8; tt++) {
                const int bn = tt * 8 + (l >> 2);
                uint32_t b0 = *(const uint32_t*)(Bs + bn * AROW + k0);
                uint32_t b1 = *(const uint32_t*)(Bs + bn * AROW + k0 + 8);
                mma_bf16(acc[tt], a0, a1, a2, a3, b0, b1);
            }
        }

        // s = e2 - 2*dot (row-constant sz cancels in argmin); store fp16.
        {
            const size_t rA = (size_t)(nbase + rsub) * K_CODES;
            const size_t rB = rA + 8 * K_CODES;
            #pragma unroll
            for (int tt = 0; tt < 8; tt++) {
                const int nl = tt * 8 + 2 * (l & 3);
                const int n0 = c * 64 + nl;
                const float e2a = e2s[nl], e2b = e2s[nl + 1];
                float sA0 = __fmaf_rn(-2.0f, acc[tt][0], e2a);
                float sA1 = __fmaf_rn(-2.0f, acc[tt][1], e2b);
                float sB0 = __fmaf_rn(-2.0f, acc[tt][2], e2a);
                float sB1 = __fmaf_rn(-2.0f, acc[tt][3], e2b);
                *(__half2*)&g_dh[rA + n0] = __floats2half2_rn(sA0, sA1);
                *(__half2*)&g_dh[rB + n0] = __floats2half2_rn(sB0, sB1);
            }
        }
        __syncthreads();
    }
}

// ---- pass 2: tight band on fp16 s-values + warp-cooperative exact rescore ----
__global__ void argmin_kernel(const float* __restrict__ emb,
                              float* __restrict__ idxf) {
    __shared__ unsigned short cand[8][1024];   // 16 KB, no overflow possible
    __shared__ int ccnt[8];
    const int wrp = threadIdx.x >> 5;
    const int row = blockIdx.x * 8 + wrp;
    const int l = threadIdx.x & 31;
    if (l == 0) ccnt[wrp] = 0;
    __syncwarp();

    const uint4* dr4 = (const uint4*)(g_dh + (size_t)row * K_CODES);
    float sv[4][8];
    float m = 3.402823466e38f;
    #pragma unroll
    for (int i = 0; i < 4; i++) {
        uint4 vv = dr4[i * 32 + l];             // 8 halfs: codes (i*32+l)*8..+7
        float2 f0 = __half22float2(*(__half2*)&vv.x);
        float2 f1 = __half22float2(*(__half2*)&vv.y);
        float2 f2 = __half22float2(*(__half2*)&vv.z);
        float2 f3 = __half22float2(*(__half2*)&vv.w);
        sv[i][0] = f0.x; sv[i][1] = f0.y; sv[i][2] = f1.x; sv[i][3] = f1.y;
        sv[i][4] = f2.x; sv[i][5] = f2.y; sv[i][6] = f3.x; sv[i][7] = f3.y;
        #pragma unroll
        for (int u = 0; u < 8; u++) m = fminf(m, sv[i][u]);
    }
    #pragma unroll
    for (int o = 16; o > 0; o >>= 1)
        m = fminf(m, __shfl_xor_sync(0xFFFFFFFFu, m, o));

    const float sz = g_sz[row];
    // band >= 2*(bf16 MMA err + fp16 quant err) with ~2x slack:
    const float band = 5e-4f * sqrtf(sz) + 2e-4f;   // ~8.2e-3
    const float th = m + band;

    #pragma unroll
    for (int i = 0; i < 4; i++) {
        #pragma unroll
        for (int u = 0; u < 8; u++) {
            if (sv[i][u] <= th) {
                int p = atomicAdd(&ccnt[wrp], 1);
                cand[wrp][p] = (unsigned short)((i * 32 + l) * 8 + u);
            }
        }
    }
    __syncwarp();
    const int cnt = ccnt[wrp];

    const float* zr = g_zf + (size_t)row * D_DIM;
    float zseg[8];
    #pragma unroll
    for (int u = 0; u < 8; u++) zseg[u] = zr[l * 8 + u];

    unsigned long long best = ~0ULL;
    for (int ci = 0; ci < cnt; ci++) {
        const int code = cand[wrp][ci];
        const float* er = emb + (size_t)code * D_DIM + l * 8;
        float part = 0.f;
        #pragma unroll
        for (int u = 0; u < 8; u++)
            part = __fmaf_rn(zseg[u], __ldg(&er[u]), part);
        #pragma unroll
        for (int o = 16; o > 0; o >>= 1)
            part = __fadd_rn(part, __shfl_xor_sync(0xFFFFFFFFu, part, o));
        float tt = __fadd_rn(sz, g_e2[code]);
        float dist = __fmaf_rn(-2.0f, part, tt);
        unsigned fb = __float_as_uint(dist);
        fb = (fb & 0x80000000u) ? ~fb : (fb | 0x80000000u);
        unsigned long long p =
            ((unsigned long long)fb << 32) | (unsigned long long)code;
        if (p < best) best = p;    // lowest dist, lowest code on ties
    }
    if (l == 0) {
        const unsigned code = (unsigned)(best & 0xFFFFFFFFu);
        g_code[row] = code;
        idxf[row] = (float)code;
    }
}

// ---- epilogue: zq + loss (identical since R7) ----
__global__ void epi_kernel(const float* __restrict__ z,
                           const float* __restrict__ emb,
                           float* __restrict__ zq, float* __restrict__ loss) {
    const int nbase = blockIdx.x * 128;
    const int b = nbase / HW;
    const int hwbase = nbase % HW;
    const float* zb = z + (size_t)b * (D_DIM * HW) + hwbase;
    const int tid = threadIdx.x;
    const int r = tid & 127;
    const int half = tid >> 7;
    const int n = nbase + r;
    const unsigned code = g_code[n];
    const float* erow = emb + (size_t)code * D_DIM;
    float* zqb = zq + (size_t)b * (D_DIM * HW) + hwbase;
    float* lrow = loss + (size_t)n * D_DIM;
    #pragma unroll 4
    for (int sft = 0; sft < D_DIM / 2; sft++) {
        const int d = half * (D_DIM / 2) + sft;
        float zv = zb[(size_t)d * HW + r];
        float ev = __ldg(&erow[d]);
        zqb[(size_t)d * HW + r] = ev;
        float df = __fadd_rn(ev, -zv);
        lrow[d] = __fmul_rn(df, df);
    }
}

extern "C" void kernel_launch(void* const* d_in, const int* in_sizes, int n_in,
                              void* d_out, int out_size) {
    const float* z   = (const float*)d_in[0];   // [32,256,32,32]
    const float* emb = (const float*)d_in[1];   // [1024,256]
    float* out = (float*)d_out;

    const int n_z = in_sizes[0];                // 8388608
    const int N = n_z / D_DIM;                  // 32768

    float* zq   = out;
    float* idxf = out + n_z;
    float* loss = out + n_z + N;

    cudaFuncSetAttribute(mma_kernel,
                         cudaFuncAttributeMaxDynamicSharedMemorySize,
                         SMEM_C_TOTAL);

    vq_prep<<<K_CODES, D_DIM>>>(emb);
    zt_kernel<<<dim3(HW / 64, D_DIM / 64, 32), 256>>>(z);
    sz_kernel<<<N / 128, 128>>>(z);
    mma_kernel<<<N / 128, 256, SMEM_C_TOTAL>>>();
    argmin_kernel<<<N / 8, 256>>>(emb, idxf);
    epi_kernel<<<N / 128, 256>>>(z, emb, zq, loss);
}